// round 2
// baseline (speedup 1.0000x reference)
#include <cuda_runtime.h>

// Problem constants
#define DD   16    // model dim
#define HH   8     // heads (head dim = 2)
#define LL   8     // layers
#define FFD  16    // ffn dim
#define KK   35    // conv kernel / patch size
#define PP   100   // patches = 3500/35
#define SS   101   // tokens = PP + cls
#define SEQ  3500
#define NTHREADS 128

__device__ __forceinline__ void ln16(float* v, const float* __restrict__ g,
                                     const float* __restrict__ bt) {
    float mu = 0.f;
    #pragma unroll
    for (int d = 0; d < DD; d++) mu += v[d];
    mu *= (1.0f / DD);
    float var = 0.f;
    #pragma unroll
    for (int d = 0; d < DD; d++) { float c = v[d] - mu; var += c * c; }
    float rs = rsqrtf(var * (1.0f / DD) + 1e-5f);
    #pragma unroll
    for (int d = 0; d < DD; d++) v[d] = (v[d] - mu) * rs * g[d] + bt[d];
}

__global__ __launch_bounds__(NTHREADS) void torrin_transformer_kernel(
    const float* __restrict__ x,      const float* __restrict__ conv_w,
    const float* __restrict__ conv_b, const float* __restrict__ cls_emb,
    const float* __restrict__ Wqkv,   const float* __restrict__ bqkv,
    const float* __restrict__ Wo,     const float* __restrict__ bo,
    const float* __restrict__ W1,     const float* __restrict__ b1,
    const float* __restrict__ W2,     const float* __restrict__ b2,
    const float* __restrict__ ln1_g,  const float* __restrict__ ln1_b,
    const float* __restrict__ ln2_g,  const float* __restrict__ ln2_b,
    const float* __restrict__ lnf_g,  const float* __restrict__ lnf_b,
    const float* __restrict__ end_w,  const float* __restrict__ end_b,
    const float* __restrict__ head_w, const float* __restrict__ head_b,
    float* __restrict__ out)
{
    // big: staging for x during conv (3500 f), then k|v (2*101*16 = 3232 f)
    __shared__ __align__(16) float big[SEQ];
    __shared__ __align__(16) float w_qkv[48 * DD];   // also conv_w staging (560 <= 768)
    __shared__ __align__(16) float w_o[DD * DD];
    __shared__ __align__(16) float w_1[FFD * DD];
    __shared__ __align__(16) float w_2[DD * FFD];
    __shared__ float b_qkv[48];
    __shared__ float b_o[DD], b_1[FFD], b_2[DD];
    __shared__ float g1s[DD], be1s[DD], g2s[DD], be2s[DD];
    __shared__ float clat[DD + PP + 12];             // cls + latent scratch

    const int tid = threadIdx.x;
    const int bidx = blockIdx.x;

    // ---- stage x row + conv weights ----
    const float* xb = x + (size_t)bidx * SEQ;
    for (int i = tid; i < SEQ; i += NTHREADS) big[i] = xb[i];
    for (int i = tid; i < DD * KK; i += NTHREADS) w_qkv[i] = conv_w[i];
    if (tid < DD) b_o[tid] = conv_b[tid];   // reuse b_o as conv_b staging
    __syncthreads();

    // ---- conv front-end: h[s][f] ----
    float h[DD];
    if (tid == 0) {
        #pragma unroll
        for (int f = 0; f < DD; f++) h[f] = cls_emb[f];
    } else if (tid < SS) {
        const int p = tid - 1;
        float xp[KK];
        #pragma unroll
        for (int k = 0; k < KK; k++) xp[k] = big[p * KK + k];
        #pragma unroll
        for (int f = 0; f < DD; f++) {
            float acc = b_o[f];
            #pragma unroll
            for (int k = 0; k < KK; k++) acc += xp[k] * w_qkv[f * KK + k];
            h[f] = acc;
        }
    }

    float* ksh = big;             // 101*16
    float* vsh = big + SS * DD;   // 101*16  (total 3232 <= 3500)

    // scale folded with log2(e) so scores go straight into exp2f
    const float QSCALE = 0.70710678118654752f * 1.44269504088896340f;

    for (int l = 0; l < LL; l++) {
        __syncthreads();   // prior reads of big / weight arrays complete
        for (int i = tid; i < 48 * DD; i += NTHREADS) w_qkv[i] = Wqkv[l * 48 * DD + i];
        for (int i = tid; i < DD * DD; i += NTHREADS) {
            w_o[i] = Wo[l * DD * DD + i];
            w_1[i] = W1[l * FFD * DD + i];
            w_2[i] = W2[l * DD * FFD + i];
        }
        if (tid < 48) b_qkv[tid] = bqkv[l * 48 + tid];
        if (tid < DD) {
            b_o[tid]  = bo[l * DD + tid];
            b_1[tid]  = b1[l * FFD + tid];
            b_2[tid]  = b2[l * DD + tid];
            g1s[tid]  = ln1_g[l * DD + tid];
            be1s[tid] = ln1_b[l * DD + tid];
            g2s[tid]  = ln2_g[l * DD + tid];
            be2s[tid] = ln2_b[l * DD + tid];
        }
        __syncthreads();

        float q[DD];
        if (tid < SS) {
            // ---- QKV projection: 48x16 (weights broadcast from smem as float4) ----
            float kv_reg[32];
            const float4* wq4 = (const float4*)w_qkv;
            #pragma unroll
            for (int e = 0; e < 48; e++) {
                float acc = b_qkv[e];
                #pragma unroll
                for (int d4 = 0; d4 < 4; d4++) {
                    float4 w = wq4[e * 4 + d4];
                    acc += h[d4*4+0]*w.x + h[d4*4+1]*w.y + h[d4*4+2]*w.z + h[d4*4+3]*w.w;
                }
                if (e < 16)      q[e] = acc;
                else             kv_reg[e - 16] = acc;
            }
            #pragma unroll
            for (int i = 0; i < DD; i++) q[i] *= QSCALE;  // fold scale*log2e into q
            float4* k4 = (float4*)(ksh + tid * DD);
            float4* v4 = (float4*)(vsh + tid * DD);
            #pragma unroll
            for (int j = 0; j < 4; j++) {
                k4[j] = make_float4(kv_reg[j*4+0], kv_reg[j*4+1], kv_reg[j*4+2], kv_reg[j*4+3]);
                v4[j] = make_float4(kv_reg[16+j*4+0], kv_reg[16+j*4+1], kv_reg[16+j*4+2], kv_reg[16+j*4+3]);
            }
        }
        __syncthreads();

        if (tid < SS) {
            // ---- attention: single-pass softmax (scores bounded, no max needed) ----
            float lsum[HH];
            float acc[DD];
            #pragma unroll
            for (int hh = 0; hh < HH; hh++) lsum[hh] = 0.f;
            #pragma unroll
            for (int d = 0; d < DD; d++) acc[d] = 0.f;

            for (int t = 0; t < SS; t++) {
                const float4* kt = (const float4*)(ksh + t * DD);
                const float4* vt = (const float4*)(vsh + t * DD);
                float kk[DD], vv[DD];
                #pragma unroll
                for (int j = 0; j < 4; j++) {
                    float4 a = kt[j];
                    kk[j*4+0]=a.x; kk[j*4+1]=a.y; kk[j*4+2]=a.z; kk[j*4+3]=a.w;
                    float4 c = vt[j];
                    vv[j*4+0]=c.x; vv[j*4+1]=c.y; vv[j*4+2]=c.z; vv[j*4+3]=c.w;
                }
                #pragma unroll
                for (int hh = 0; hh < HH; hh++) {
                    float sc = q[2*hh] * kk[2*hh] + q[2*hh+1] * kk[2*hh+1]; // = score*log2e
                    float p  = exp2f(sc);                                    // = e^score
                    lsum[hh]   += p;
                    acc[2*hh]   += p * vv[2*hh];
                    acc[2*hh+1] += p * vv[2*hh+1];
                }
            }

            float ctx[DD];
            #pragma unroll
            for (int hh = 0; hh < HH; hh++) {
                float r = 1.0f / lsum[hh];
                ctx[2*hh]   = acc[2*hh]   * r;
                ctx[2*hh+1] = acc[2*hh+1] * r;
            }

            // ---- output proj + residual + LN1 ----
            float hn[DD];
            const float4* wo4 = (const float4*)w_o;
            #pragma unroll
            for (int o = 0; o < DD; o++) {
                float a2 = b_o[o];
                #pragma unroll
                for (int d4 = 0; d4 < 4; d4++) {
                    float4 w = wo4[o * 4 + d4];
                    a2 += ctx[d4*4+0]*w.x + ctx[d4*4+1]*w.y + ctx[d4*4+2]*w.z + ctx[d4*4+3]*w.w;
                }
                hn[o] = h[o] + a2;
            }
            ln16(hn, g1s, be1s);

            // ---- FFN + residual + LN2 ----
            float f[FFD];
            const float4* w14 = (const float4*)w_1;
            #pragma unroll
            for (int j = 0; j < FFD; j++) {
                float a2 = b_1[j];
                #pragma unroll
                for (int d4 = 0; d4 < 4; d4++) {
                    float4 w = w14[j * 4 + d4];
                    a2 += hn[d4*4+0]*w.x + hn[d4*4+1]*w.y + hn[d4*4+2]*w.z + hn[d4*4+3]*w.w;
                }
                f[j] = fmaxf(a2, 0.f);
            }
            const float4* w24 = (const float4*)w_2;
            #pragma unroll
            for (int d = 0; d < DD; d++) {
                float a2 = b_2[d];
                #pragma unroll
                for (int j4 = 0; j4 < 4; j4++) {
                    float4 w = w24[d * 4 + j4];
                    a2 += f[j4*4+0]*w.x + f[j4*4+1]*w.y + f[j4*4+2]*w.z + f[j4*4+3]*w.w;
                }
                h[d] = hn[d] + a2;
            }
            ln16(h, g2s, be2s);
        }
    }

    // ---- final LN (only cls token actually matters, but keep uniform) ----
    if (tid == 0) {
        float gf[DD], bf[DD];
        #pragma unroll
        for (int d = 0; d < DD; d++) { gf[d] = lnf_g[d]; bf[d] = lnf_b[d]; }
        ln16(h, gf, bf);
        #pragma unroll
        for (int d = 0; d < DD; d++) clat[d] = h[d];
    }
    __syncthreads();

    // ---- head: latent = cls @ end_w^T + end_b ----
    if (tid < PP) {
        float acc = end_b[tid];
        const float* ew = end_w + tid * DD;
        #pragma unroll
        for (int d = 0; d < DD; d++) acc += clat[d] * ew[d];
        clat[DD + tid] = acc;
    }
    __syncthreads();

    if (tid == 0) {
        float z = head_b[0];
        #pragma unroll 4
        for (int j = 0; j < PP; j++) z += clat[DD + j] * head_w[j];
        out[bidx] = 1.0f / (1.0f + __expf(-z));
    }
}

extern "C" void kernel_launch(void* const* d_in, const int* in_sizes, int n_in,
                              void* d_out, int out_size) {
    const float* x       = (const float*)d_in[0];
    const float* conv_w  = (const float*)d_in[1];
    const float* conv_b  = (const float*)d_in[2];
    const float* cls_emb = (const float*)d_in[3];
    const float* Wqkv    = (const float*)d_in[4];
    const float* bqkv    = (const float*)d_in[5];
    const float* Wo      = (const float*)d_in[6];
    const float* bo      = (const float*)d_in[7];
    const float* W1      = (const float*)d_in[8];
    const float* b1      = (const float*)d_in[9];
    const float* W2      = (const float*)d_in[10];
    const float* b2      = (const float*)d_in[11];
    const float* ln1_g   = (const float*)d_in[12];
    const float* ln1_b   = (const float*)d_in[13];
    const float* ln2_g   = (const float*)d_in[14];
    const float* ln2_b   = (const float*)d_in[15];
    const float* lnf_g   = (const float*)d_in[16];
    const float* lnf_b   = (const float*)d_in[17];
    const float* end_w   = (const float*)d_in[18];
    const float* end_b   = (const float*)d_in[19];
    const float* head_w  = (const float*)d_in[20];
    const float* head_b  = (const float*)d_in[21];
    float* out = (float*)d_out;

    const int B = in_sizes[0] / SEQ;   // 2048
    torrin_transformer_kernel<<<B, NTHREADS>>>(
        x, conv_w, conv_b, cls_emb, Wqkv, bqkv, Wo, bo, W1, b1, W2, b2,
        ln1_g, ln1_b, ln2_g, ln2_b, lnf_g, lnf_b, end_w, end_b, head_w, head_b,
        out);
}

// round 5
// speedup vs baseline: 1.1448x; 1.1448x over previous
#include <cuda_runtime.h>

#define DD   16
#define HH   8
#define LL   8
#define FFD  16
#define KK   35
#define PP   100
#define SS   101
#define SEQ  3500
#define NT   128

typedef unsigned long long u64;

// ---- f32x2 packed helpers (sm_103a FFMA2 path; ptxas won't emit these from C++) ----
__device__ __forceinline__ u64 pk(float a, float b) {
    u64 r; asm("mov.b64 %0,{%1,%2};" : "=l"(r) : "f"(a), "f"(b)); return r;
}
__device__ __forceinline__ void upk(float& a, float& b, u64 x) {
    asm("mov.b64 {%0,%1},%2;" : "=f"(a), "=f"(b) : "l"(x));
}
__device__ __forceinline__ u64 fma2_(u64 a, u64 b, u64 c) {
    u64 r; asm("fma.rn.f32x2 %0,%1,%2,%3;" : "=l"(r) : "l"(a), "l"(b), "l"(c)); return r;
}
__device__ __forceinline__ u64 mul2_(u64 a, u64 b) {
    u64 r; asm("mul.rn.f32x2 %0,%1,%2;" : "=l"(r) : "l"(a), "l"(b)); return r;
}
__device__ __forceinline__ u64 add2_(u64 a, u64 b) {
    u64 r; asm("add.rn.f32x2 %0,%1,%2;" : "=l"(r) : "l"(a), "l"(b)); return r;
}
__device__ __forceinline__ float ex2a(float x) {
    float r; asm("ex2.approx.f32 %0,%1;" : "=f"(r) : "f"(x)); return r;
}
__device__ __forceinline__ float rcpa(float x) {
    float r; asm("rcp.approx.f32 %0,%1;" : "=f"(r) : "f"(x)); return r;
}

// packed LayerNorm over 8 float2 pairs (16 values)
__device__ __forceinline__ void ln2p(u64* v, const u64* g2, const u64* b2) {
    u64 s = add2_(add2_(add2_(v[0], v[1]), add2_(v[2], v[3])),
                  add2_(add2_(v[4], v[5]), add2_(v[6], v[7])));
    float sl, sh; upk(sl, sh, s);
    float mu = (sl + sh) * (1.0f / 16.0f);
    u64 nm = pk(-mu, -mu);
    u64 c[8];
    #pragma unroll
    for (int j = 0; j < 8; j++) c[j] = add2_(v[j], nm);
    u64 q = add2_(add2_(add2_(mul2_(c[0], c[0]), mul2_(c[1], c[1])),
                        add2_(mul2_(c[2], c[2]), mul2_(c[3], c[3]))),
                  add2_(add2_(mul2_(c[4], c[4]), mul2_(c[5], c[5])),
                        add2_(mul2_(c[6], c[6]), mul2_(c[7], c[7]))));
    float ql, qh; upk(ql, qh, q);
    float rs = rsqrtf((ql + qh) * (1.0f / 16.0f) + 1e-5f);
    u64 rs2 = pk(rs, rs);
    #pragma unroll
    for (int j = 0; j < 8; j++) v[j] = fma2_(mul2_(c[j], rs2), g2[j], b2[j]);
}

// 16->16 GEMM, packed outputs: out pair p = {o[2p], o[2p+1]}, wT[d*16+o]
__device__ __forceinline__ void gemm16p(const float* in, const float* wT,
                                        const u64* b2, u64* o) {
    #pragma unroll
    for (int j = 0; j < 8; j++) o[j] = b2[j];
    #pragma unroll
    for (int d = 0; d < 16; d++) {
        u64 x = pk(in[d], in[d]);
        const ulonglong2* r = (const ulonglong2*)(wT + d * 16);
        ulonglong2 r0 = r[0], r1 = r[1], r2 = r[2], r3 = r[3];
        o[0] = fma2_(x, r0.x, o[0]); o[1] = fma2_(x, r0.y, o[1]);
        o[2] = fma2_(x, r1.x, o[2]); o[3] = fma2_(x, r1.y, o[3]);
        o[4] = fma2_(x, r2.x, o[4]); o[5] = fma2_(x, r2.y, o[5]);
        o[6] = fma2_(x, r3.x, o[6]); o[7] = fma2_(x, r3.y, o[7]);
    }
}

__device__ __forceinline__ void ln16s(float* v, const float* g, const float* bt) {
    float mu = 0.f;
    #pragma unroll
    for (int d = 0; d < DD; d++) mu += v[d];
    mu *= (1.0f / DD);
    float var = 0.f;
    #pragma unroll
    for (int d = 0; d < DD; d++) { float c = v[d] - mu; var += c * c; }
    float rs = rsqrtf(var * (1.0f / DD) + 1e-5f);
    #pragma unroll
    for (int d = 0; d < DD; d++) v[d] = (v[d] - mu) * rs * g[d] + bt[d];
}

__global__ __launch_bounds__(NT, 4) void torrin_transformer_kernel(
    const float* __restrict__ x,      const float* __restrict__ conv_w,
    const float* __restrict__ conv_b, const float* __restrict__ cls_emb,
    const float* __restrict__ Wqkv,   const float* __restrict__ bqkv,
    const float* __restrict__ Wo,     const float* __restrict__ bo,
    const float* __restrict__ W1,     const float* __restrict__ b1,
    const float* __restrict__ W2,     const float* __restrict__ b2,
    const float* __restrict__ ln1_g,  const float* __restrict__ ln1_b,
    const float* __restrict__ ln2_g,  const float* __restrict__ ln2_b,
    const float* __restrict__ lnf_g,  const float* __restrict__ lnf_b,
    const float* __restrict__ end_w,  const float* __restrict__ end_b,
    const float* __restrict__ head_w, const float* __restrict__ head_b,
    float* __restrict__ out)
{
    // big: x staging (3500 f) -> kv transposed (101 tokens * 32 f = 3232)
    __shared__ __align__(16) float big[SEQ];
    __shared__ __align__(16) float wqkvT[48 * DD];   // transposed [d][e]; conv_w staging
    __shared__ __align__(16) float woT[DD * DD];     // [d][o]
    __shared__ __align__(16) float w1T[DD * FFD];    // [d][f]
    __shared__ __align__(16) float w2T[FFD * DD];    // [f][d]
    __shared__ __align__(16) float b_qkv[48];
    __shared__ __align__(16) float b_o[DD], b_1[FFD], b_2[DD];
    __shared__ __align__(16) float g1s[DD], be1s[DD], g2s[DD], be2s[DD];
    __shared__ float clat[DD + PP + 12];

    const int tid = threadIdx.x;
    const int bidx = blockIdx.x;

    // ---- stage x row + conv weights ----
    const float* xb = x + (size_t)bidx * SEQ;
    for (int i = tid; i < SEQ; i += NT) big[i] = xb[i];
    for (int i = tid; i < DD * KK; i += NT) wqkvT[i] = conv_w[i];
    if (tid < DD) b_o[tid] = conv_b[tid];
    __syncthreads();

    // ---- conv front-end ----
    float hs0[DD];
    if (tid == 0) {
        #pragma unroll
        for (int f = 0; f < DD; f++) hs0[f] = cls_emb[f];
    } else if (tid < SS) {
        const int p = tid - 1;
        float xp[KK];
        #pragma unroll
        for (int k = 0; k < KK; k++) xp[k] = big[p * KK + k];
        #pragma unroll
        for (int f = 0; f < DD; f++) {
            float acc = b_o[f];
            #pragma unroll
            for (int k = 0; k < KK; k++) acc += xp[k] * wqkvT[f * KK + k];
            hs0[f] = acc;
        }
    } else {
        #pragma unroll
        for (int f = 0; f < DD; f++) hs0[f] = 0.f;
    }
    // residual state packed: h2[j] = {h[2j], h[2j+1]}
    u64 h2[8];
    #pragma unroll
    for (int j = 0; j < 8; j++) h2[j] = pk(hs0[2 * j], hs0[2 * j + 1]);

    float* kvsh = big;   // 101 tokens * 32 floats (kT0|kT1|vT0|vT1) = 128B/token

    const float QSC = 0.70710678118654752f * 1.44269504088896340f;
    const u64 QS2 = pk(QSC, QSC);

    for (int l = 0; l < LL; l++) {
        __syncthreads();   // previous reads of big/weights complete
        // ---- stage weights (transposed) ----
        for (int i = tid; i < 48 * DD; i += NT) {
            int d = i / 48, e = i - d * 48;
            wqkvT[i] = Wqkv[l * 48 * DD + e * DD + d];
        }
        for (int i = tid; i < DD * DD; i += NT) {
            int a = i >> 4, bb = i & 15;          // i = a*16 + bb
            int t = bb * DD + a;                  // transpose index
            woT[i] = Wo[l * DD * DD + t];
            w1T[i] = W1[l * FFD * DD + t];
            w2T[i] = W2[l * DD * FFD + t];
        }
        if (tid < 48) b_qkv[tid] = bqkv[l * 48 + tid];
        if (tid < DD) {
            b_o[tid]  = bo[l * DD + tid];
            b_1[tid]  = b1[l * FFD + tid];
            b_2[tid]  = b2[l * DD + tid];
            g1s[tid]  = ln1_g[l * DD + tid];
            be1s[tid] = ln1_b[l * DD + tid];
            g2s[tid]  = ln2_g[l * DD + tid];
            be2s[tid] = ln2_b[l * DD + tid];
        }
        __syncthreads();

        u64 q0[4], q1[4];   // packed q: q0[p]={q[4p],q[4p+2]}*QS, q1[p]={q[4p+1],q[4p+3]}*QS
        if (tid < SS) {
            // ---- QKV projection: 48 outputs as 24 packed pairs ----
            u64 acc[24];
            const u64* bq2 = (const u64*)b_qkv;
            #pragma unroll
            for (int j = 0; j < 24; j++) acc[j] = bq2[j];
            float hs[16];
            #pragma unroll
            for (int j = 0; j < 8; j++) upk(hs[2 * j], hs[2 * j + 1], h2[j]);
            #pragma unroll
            for (int d = 0; d < 16; d++) {
                u64 xd = pk(hs[d], hs[d]);
                const ulonglong2* r = (const ulonglong2*)(wqkvT + d * 48);
                #pragma unroll
                for (int j = 0; j < 12; j++) {       // FIX: 12 ulonglong2 = all 48 weights
                    ulonglong2 rr = r[j];
                    acc[2 * j]     = fma2_(xd, rr.x, acc[2 * j]);
                    acc[2 * j + 1] = fma2_(xd, rr.y, acc[2 * j + 1]);
                }
            }
            // q repack to per-dim head pairs
            float qs[16];
            #pragma unroll
            for (int j = 0; j < 8; j++) upk(qs[2 * j], qs[2 * j + 1], acc[j]);
            #pragma unroll
            for (int p = 0; p < 4; p++) {
                q0[p] = mul2_(pk(qs[4 * p], qs[4 * p + 2]), QS2);
                q1[p] = mul2_(pk(qs[4 * p + 1], qs[4 * p + 3]), QS2);
            }
            // kv transposed store: kT0[j]=k[2j], kT1[j]=k[2j+1], vT0, vT1
            float* kt = kvsh + tid * 32;
            #pragma unroll
            for (int j = 0; j < 8; j++) {
                float a, b; upk(a, b, acc[8 + j]);
                kt[j] = a; kt[8 + j] = b;
            }
            #pragma unroll
            for (int j = 0; j < 8; j++) {
                float a, b; upk(a, b, acc[16 + j]);
                kt[16 + j] = a; kt[24 + j] = b;
            }
        }
        __syncthreads();

        if (tid < SS) {
            // ---- attention: packed single-pass softmax ----
            u64 ls[4], a0[4], a1[4];
            #pragma unroll
            for (int p = 0; p < 4; p++) { ls[p] = 0ULL; a0[p] = 0ULL; a1[p] = 0ULL; }
            const ulonglong2* kvp = (const ulonglong2*)kvsh;

            for (int t = 0; t < SS; t++) {
                const ulonglong2* pr = kvp + t * 8;
                ulonglong2 K0 = pr[0], K1 = pr[1];   // kT0: head pairs {01},{23} / {45},{67}
                ulonglong2 L0 = pr[2], L1 = pr[3];   // kT1
                ulonglong2 V0 = pr[4], V1 = pr[5];   // vT0
                ulonglong2 U0 = pr[6], U1 = pr[7];   // vT1
                {
                    u64 sc = fma2_(q1[0], L0.x, mul2_(q0[0], K0.x));
                    float lo, hi; upk(lo, hi, sc);
                    u64 pp = pk(ex2a(lo), ex2a(hi));
                    ls[0] = add2_(ls[0], pp);
                    a0[0] = fma2_(pp, V0.x, a0[0]);
                    a1[0] = fma2_(pp, U0.x, a1[0]);
                }
                {
                    u64 sc = fma2_(q1[1], L0.y, mul2_(q0[1], K0.y));
                    float lo, hi; upk(lo, hi, sc);
                    u64 pp = pk(ex2a(lo), ex2a(hi));
                    ls[1] = add2_(ls[1], pp);
                    a0[1] = fma2_(pp, V0.y, a0[1]);
                    a1[1] = fma2_(pp, U0.y, a1[1]);
                }
                {
                    u64 sc = fma2_(q1[2], L1.x, mul2_(q0[2], K1.x));
                    float lo, hi; upk(lo, hi, sc);
                    u64 pp = pk(ex2a(lo), ex2a(hi));
                    ls[2] = add2_(ls[2], pp);
                    a0[2] = fma2_(pp, V1.x, a0[2]);
                    a1[2] = fma2_(pp, U1.x, a1[2]);
                }
                {
                    u64 sc = fma2_(q1[3], L1.y, mul2_(q0[3], K1.y));
                    float lo, hi; upk(lo, hi, sc);
                    u64 pp = pk(ex2a(lo), ex2a(hi));
                    ls[3] = add2_(ls[3], pp);
                    a0[3] = fma2_(pp, V1.y, a0[3]);
                    a1[3] = fma2_(pp, U1.y, a1[3]);
                }
            }

            // ---- ctx (natural order) ----
            float cx[16];
            #pragma unroll
            for (int p = 0; p < 4; p++) {
                float s0, s1; upk(s0, s1, ls[p]);
                float r0 = rcpa(s0), r1 = rcpa(s1);
                float x0, x1; upk(x0, x1, a0[p]);
                float y0, y1; upk(y0, y1, a1[p]);
                cx[4 * p]     = x0 * r0;
                cx[4 * p + 1] = y0 * r0;
                cx[4 * p + 2] = x1 * r1;
                cx[4 * p + 3] = y1 * r1;
            }

            // ---- Wo + residual + LN1 (packed) ----
            u64 hn2[8];
            gemm16p(cx, woT, (const u64*)b_o, hn2);
            #pragma unroll
            for (int j = 0; j < 8; j++) hn2[j] = add2_(h2[j], hn2[j]);
            ln2p(hn2, (const u64*)g1s, (const u64*)be1s);

            // ---- FFN ----
            float hs[16];
            #pragma unroll
            for (int j = 0; j < 8; j++) upk(hs[2 * j], hs[2 * j + 1], hn2[j]);
            u64 f2[8];
            gemm16p(hs, w1T, (const u64*)b_1, f2);
            float fs[16];
            #pragma unroll
            for (int j = 0; j < 8; j++) {
                float a, b; upk(a, b, f2[j]);
                fs[2 * j]     = fmaxf(a, 0.f);
                fs[2 * j + 1] = fmaxf(b, 0.f);
            }
            u64 o2[8];
            gemm16p(fs, w2T, (const u64*)b_2, o2);
            #pragma unroll
            for (int j = 0; j < 8; j++) h2[j] = add2_(hn2[j], o2[j]);
            ln2p(h2, (const u64*)g2s, (const u64*)be2s);
        }
    }

    // ---- final LN on cls only ----
    if (tid == 0) {
        float hv[16];
        #pragma unroll
        for (int j = 0; j < 8; j++) upk(hv[2 * j], hv[2 * j + 1], h2[j]);
        float gf[DD], bf[DD];
        #pragma unroll
        for (int d = 0; d < DD; d++) { gf[d] = lnf_g[d]; bf[d] = lnf_b[d]; }
        ln16s(hv, gf, bf);
        #pragma unroll
        for (int d = 0; d < DD; d++) clat[d] = hv[d];
    }
    __syncthreads();

    if (tid < PP) {
        float acc = end_b[tid];
        const float* ew = end_w + tid * DD;
        #pragma unroll
        for (int d = 0; d < DD; d++) acc += clat[d] * ew[d];
        clat[DD + tid] = acc;
    }
    __syncthreads();

    if (tid == 0) {
        float z = head_b[0];
        #pragma unroll 4
        for (int j = 0; j < PP; j++) z += clat[DD + j] * head_w[j];
        out[bidx] = 1.0f / (1.0f + __expf(-z));
    }
}

extern "C" void kernel_launch(void* const* d_in, const int* in_sizes, int n_in,
                              void* d_out, int out_size) {
    const float* x       = (const float*)d_in[0];
    const float* conv_w  = (const float*)d_in[1];
    const float* conv_b  = (const float*)d_in[2];
    const float* cls_emb = (const float*)d_in[3];
    const float* Wqkv    = (const float*)d_in[4];
    const float* bqkv    = (const float*)d_in[5];
    const float* Wo      = (const float*)d_in[6];
    const float* bo      = (const float*)d_in[7];
    const float* W1      = (const float*)d_in[8];
    const float* b1      = (const float*)d_in[9];
    const float* W2      = (const float*)d_in[10];
    const float* b2      = (const float*)d_in[11];
    const float* ln1_g   = (const float*)d_in[12];
    const float* ln1_b   = (const float*)d_in[13];
    const float* ln2_g   = (const float*)d_in[14];
    const float* ln2_b   = (const float*)d_in[15];
    const float* lnf_g   = (const float*)d_in[16];
    const float* lnf_b   = (const float*)d_in[17];
    const float* end_w   = (const float*)d_in[18];
    const float* end_b   = (const float*)d_in[19];
    const float* head_w  = (const float*)d_in[20];
    const float* head_b  = (const float*)d_in[21];
    float* out = (float*)d_out;

    const int B = in_sizes[0] / SEQ;   // 2048
    torrin_transformer_kernel<<<B, NT>>>(
        x, conv_w, conv_b, cls_emb, Wqkv, bqkv, Wo, bo, W1, b1, W2, b2,
        ln1_g, ln1_b, ln2_g, ln2_b, lnf_g, lnf_b, end_w, end_b, head_w, head_b,
        out);
}

// round 9
// speedup vs baseline: 1.2470x; 1.0893x over previous
#include <cuda_runtime.h>

#define DD   16
#define HH   8
#define LL   8
#define FFD  16
#define KK   35
#define PP   100
#define SS   101
#define SEQ  3500
#define NT   128
#define ROWF 52          // padded token row: qT0[8] qT1[8] kT0[8] kT1[8] vT0[8] vT1[8] pad[4]
#define NROW 102         // 101 tokens + 1 zeroed dummy row

typedef unsigned long long u64;

// ---- f32x2 packed helpers (sm_103a FFMA2 path) ----
__device__ __forceinline__ u64 pk(float a, float b) {
    u64 r; asm("mov.b64 %0,{%1,%2};" : "=l"(r) : "f"(a), "f"(b)); return r;
}
__device__ __forceinline__ void upk(float& a, float& b, u64 x) {
    asm("mov.b64 {%0,%1},%2;" : "=f"(a), "=f"(b) : "l"(x));
}
__device__ __forceinline__ u64 fma2_(u64 a, u64 b, u64 c) {
    u64 r; asm("fma.rn.f32x2 %0,%1,%2,%3;" : "=l"(r) : "l"(a), "l"(b), "l"(c)); return r;
}
__device__ __forceinline__ u64 mul2_(u64 a, u64 b) {
    u64 r; asm("mul.rn.f32x2 %0,%1,%2;" : "=l"(r) : "l"(a), "l"(b)); return r;
}
__device__ __forceinline__ u64 add2_(u64 a, u64 b) {
    u64 r; asm("add.rn.f32x2 %0,%1,%2;" : "=l"(r) : "l"(a), "l"(b)); return r;
}
__device__ __forceinline__ float ex2a(float x) {
    float r; asm("ex2.approx.f32 %0,%1;" : "=f"(r) : "f"(x)); return r;
}
__device__ __forceinline__ float rcpa(float x) {
    float r; asm("rcp.approx.f32 %0,%1;" : "=f"(r) : "f"(x)); return r;
}

// packed LayerNorm over 8 float2 pairs (16 values)
__device__ __forceinline__ void ln2p(u64* v, const u64* g2, const u64* b2) {
    u64 s = add2_(add2_(add2_(v[0], v[1]), add2_(v[2], v[3])),
                  add2_(add2_(v[4], v[5]), add2_(v[6], v[7])));
    float sl, sh; upk(sl, sh, s);
    float mu = (sl + sh) * (1.0f / 16.0f);
    u64 nm = pk(-mu, -mu);
    u64 c[8];
    #pragma unroll
    for (int j = 0; j < 8; j++) c[j] = add2_(v[j], nm);
    u64 q = add2_(add2_(add2_(mul2_(c[0], c[0]), mul2_(c[1], c[1])),
                        add2_(mul2_(c[2], c[2]), mul2_(c[3], c[3]))),
                  add2_(add2_(mul2_(c[4], c[4]), mul2_(c[5], c[5])),
                        add2_(mul2_(c[6], c[6]), mul2_(c[7], c[7]))));
    float ql, qh; upk(ql, qh, q);
    float rs = rsqrtf((ql + qh) * (1.0f / 16.0f) + 1e-5f);
    u64 rs2 = pk(rs, rs);
    #pragma unroll
    for (int j = 0; j < 8; j++) v[j] = fma2_(mul2_(c[j], rs2), g2[j], b2[j]);
}

// 16->16 GEMM, packed outputs: out pair p = {o[2p], o[2p+1]}, wT[d*16+o]
__device__ __forceinline__ void gemm16p(const float* in, const float* wT,
                                        const u64* b2, u64* o) {
    #pragma unroll
    for (int j = 0; j < 8; j++) o[j] = b2[j];
    #pragma unroll
    for (int d = 0; d < 16; d++) {
        u64 x = pk(in[d], in[d]);
        const ulonglong2* r = (const ulonglong2*)(wT + d * 16);
        ulonglong2 r0 = r[0], r1 = r[1], r2 = r[2], r3 = r[3];
        o[0] = fma2_(x, r0.x, o[0]); o[1] = fma2_(x, r0.y, o[1]);
        o[2] = fma2_(x, r1.x, o[2]); o[3] = fma2_(x, r1.y, o[3]);
        o[4] = fma2_(x, r2.x, o[4]); o[5] = fma2_(x, r2.y, o[5]);
        o[6] = fma2_(x, r3.x, o[6]); o[7] = fma2_(x, r3.y, o[7]);
    }
}

__device__ __forceinline__ void ln16s(float* v, const float* g, const float* bt) {
    float mu = 0.f;
    #pragma unroll
    for (int d = 0; d < DD; d++) mu += v[d];
    mu *= (1.0f / DD);
    float var = 0.f;
    #pragma unroll
    for (int d = 0; d < DD; d++) { float c = v[d] - mu; var += c * c; }
    float rs = rsqrtf(var * (1.0f / DD) + 1e-5f);
    #pragma unroll
    for (int d = 0; d < DD; d++) v[d] = (v[d] - mu) * rs * g[d] + bt[d];
}

__global__ __launch_bounds__(NT, 4) void torrin_transformer_kernel(
    const float* __restrict__ x,      const float* __restrict__ conv_w,
    const float* __restrict__ conv_b, const float* __restrict__ cls_emb,
    const float* __restrict__ Wqkv,   const float* __restrict__ bqkv,
    const float* __restrict__ Wo,     const float* __restrict__ bo,
    const float* __restrict__ W1,     const float* __restrict__ b1,
    const float* __restrict__ W2,     const float* __restrict__ b2,
    const float* __restrict__ ln1_g,  const float* __restrict__ ln1_b,
    const float* __restrict__ ln2_g,  const float* __restrict__ ln2_b,
    const float* __restrict__ lnf_g,  const float* __restrict__ lnf_b,
    const float* __restrict__ end_w,  const float* __restrict__ end_b,
    const float* __restrict__ head_w, const float* __restrict__ head_b,
    float* __restrict__ out)
{
    // big: x staging (3500 f) overlaps token-row buffer (102*52 = 5304 f)
    __shared__ __align__(16) float big[NROW * ROWF];
    __shared__ __align__(16) float wqkvT[48 * DD];   // [d][e]; conv_w staging
    __shared__ __align__(16) float woT[DD * DD];
    __shared__ __align__(16) float w1T[DD * FFD];
    __shared__ __align__(16) float w2T[FFD * DD];
    __shared__ __align__(16) float b_qkv[48];
    __shared__ __align__(16) float b_o[DD], b_1[FFD], b_2[DD];
    __shared__ __align__(16) float g1s[DD], be1s[DD], g2s[DD], be2s[DD];
    __shared__ float clat[DD + PP + 12];

    const int tid = threadIdx.x;
    const int bidx = blockIdx.x;

    // ---- stage x row + conv weights; zero dummy row 101 (floats 5252+, no overlap with x) ----
    const float* xb = x + (size_t)bidx * SEQ;
    for (int i = tid; i < SEQ; i += NT) big[i] = xb[i];
    for (int i = tid; i < ROWF; i += NT) big[101 * ROWF + i] = 0.f;
    for (int i = tid; i < DD * KK; i += NT) wqkvT[i] = conv_w[i];
    if (tid < DD) b_o[tid] = conv_b[tid];
    __syncthreads();

    // ---- conv front-end ----
    float hs0[DD];
    if (tid == 0) {
        #pragma unroll
        for (int f = 0; f < DD; f++) hs0[f] = cls_emb[f];
    } else if (tid < SS) {
        const int p = tid - 1;
        float xp[KK];
        #pragma unroll
        for (int k = 0; k < KK; k++) xp[k] = big[p * KK + k];
        #pragma unroll
        for (int f = 0; f < DD; f++) {
            float acc = b_o[f];
            #pragma unroll
            for (int k = 0; k < KK; k++) acc += xp[k] * wqkvT[f * KK + k];
            hs0[f] = acc;
        }
    } else {
        #pragma unroll
        for (int f = 0; f < DD; f++) hs0[f] = 0.f;
    }
    u64 h2[8];
    #pragma unroll
    for (int j = 0; j < 8; j++) h2[j] = pk(hs0[2 * j], hs0[2 * j + 1]);

    const float QSC = 0.70710678118654752f * 1.44269504088896340f;
    const u64 QS2 = pk(QSC, QSC);

    // attention work assignment: grp = head half, this thread owns tokens t0,t1
    const int grp = tid >> 6;          // 0: heads 0-3 (pairs 0,1), 1: heads 4-7 (pairs 2,3)
    const int jj  = tid & 63;
    const int t0 = 2 * jj, t1 = 2 * jj + 1;
    const int r0 = (t0 < SS) ? t0 : 101;
    const int r1 = (t1 < SS) ? t1 : 101;

    for (int l = 0; l < LL; l++) {
        __syncthreads();
        // ---- stage weights (transposed) ----
        for (int i = tid; i < 48 * DD; i += NT) {
            int d = i / 48, e = i - d * 48;
            wqkvT[i] = Wqkv[l * 48 * DD + e * DD + d];
        }
        for (int i = tid; i < DD * DD; i += NT) {
            int a = i >> 4, bb = i & 15;
            int t = bb * DD + a;
            woT[i] = Wo[l * DD * DD + t];
            w1T[i] = W1[l * FFD * DD + t];
            w2T[i] = W2[l * DD * FFD + t];
        }
        if (tid < 48) b_qkv[tid] = bqkv[l * 48 + tid];
        if (tid < DD) {
            b_o[tid]  = bo[l * DD + tid];
            b_1[tid]  = b1[l * FFD + tid];
            b_2[tid]  = b2[l * DD + tid];
            g1s[tid]  = ln1_g[l * DD + tid];
            be1s[tid] = ln1_b[l * DD + tid];
            g2s[tid]  = ln2_g[l * DD + tid];
            be2s[tid] = ln2_b[l * DD + tid];
        }
        __syncthreads();

        // ---- QKV projection (1 token/thread), store q(scaled)/k/v transposed ----
        if (tid < SS) {
            u64 acc[24];
            const u64* bq2 = (const u64*)b_qkv;
            #pragma unroll
            for (int j = 0; j < 24; j++) acc[j] = bq2[j];
            float hs[16];
            #pragma unroll
            for (int j = 0; j < 8; j++) upk(hs[2 * j], hs[2 * j + 1], h2[j]);
            #pragma unroll
            for (int d = 0; d < 16; d++) {
                u64 xd = pk(hs[d], hs[d]);
                const ulonglong2* r = (const ulonglong2*)(wqkvT + d * 48);
                #pragma unroll
                for (int j = 0; j < 12; j++) {
                    ulonglong2 rr = r[j];
                    acc[2 * j]     = fma2_(xd, rr.x, acc[2 * j]);
                    acc[2 * j + 1] = fma2_(xd, rr.y, acc[2 * j + 1]);
                }
            }
            float* row = big + tid * ROWF;
            float q0v[8], q1v[8];
            #pragma unroll
            for (int j = 0; j < 8; j++) {
                u64 s2 = mul2_(acc[j], QS2);
                upk(q0v[j], q1v[j], s2);
            }
            *(float4*)(row + 0)  = make_float4(q0v[0], q0v[1], q0v[2], q0v[3]);
            *(float4*)(row + 4)  = make_float4(q0v[4], q0v[5], q0v[6], q0v[7]);
            *(float4*)(row + 8)  = make_float4(q1v[0], q1v[1], q1v[2], q1v[3]);
            *(float4*)(row + 12) = make_float4(q1v[4], q1v[5], q1v[6], q1v[7]);
            float k0v[8], k1v[8], v0v[8], v1v[8];
            #pragma unroll
            for (int j = 0; j < 8; j++) upk(k0v[j], k1v[j], acc[8 + j]);
            #pragma unroll
            for (int j = 0; j < 8; j++) upk(v0v[j], v1v[j], acc[16 + j]);
            *(float4*)(row + 16) = make_float4(k0v[0], k0v[1], k0v[2], k0v[3]);
            *(float4*)(row + 20) = make_float4(k0v[4], k0v[5], k0v[6], k0v[7]);
            *(float4*)(row + 24) = make_float4(k1v[0], k1v[1], k1v[2], k1v[3]);
            *(float4*)(row + 28) = make_float4(k1v[4], k1v[5], k1v[6], k1v[7]);
            *(float4*)(row + 32) = make_float4(v0v[0], v0v[1], v0v[2], v0v[3]);
            *(float4*)(row + 36) = make_float4(v0v[4], v0v[5], v0v[6], v0v[7]);
            *(float4*)(row + 40) = make_float4(v1v[0], v1v[1], v1v[2], v1v[3]);
            *(float4*)(row + 44) = make_float4(v1v[4], v1v[5], v1v[6], v1v[7]);
        }
        __syncthreads();

        // ---- attention: 2 tokens x 2 head-pairs per thread, half-kv loads ----
        ulonglong2 qa0 = *(const ulonglong2*)(big + r0 * ROWF + 4 * grp);
        ulonglong2 qa1 = *(const ulonglong2*)(big + r0 * ROWF + 8 + 4 * grp);
        ulonglong2 qb0 = *(const ulonglong2*)(big + r1 * ROWF + 4 * grp);
        ulonglong2 qb1 = *(const ulonglong2*)(big + r1 * ROWF + 8 + 4 * grp);

        u64 lsA0 = 0, lsA1 = 0, lsB0 = 0, lsB1 = 0;
        u64 xA0 = 0, xA1 = 0, xB0 = 0, xB1 = 0;
        u64 yA0 = 0, yA1 = 0, yB0 = 0, yB1 = 0;

        const float* kv = big + 16 + 4 * grp;
        for (int t = 0; t < SS; t++, kv += ROWF) {
            ulonglong2 K = *(const ulonglong2*)(kv);
            ulonglong2 L = *(const ulonglong2*)(kv + 8);
            ulonglong2 V = *(const ulonglong2*)(kv + 16);
            ulonglong2 U = *(const ulonglong2*)(kv + 24);
            {
                u64 sc = fma2_(qa1.x, L.x, mul2_(qa0.x, K.x));
                float lo, hi; upk(lo, hi, sc);
                u64 pp = pk(ex2a(lo), ex2a(hi));
                lsA0 = add2_(lsA0, pp);
                xA0 = fma2_(pp, V.x, xA0);
                yA0 = fma2_(pp, U.x, yA0);
            }
            {
                u64 sc = fma2_(qa1.y, L.y, mul2_(qa0.y, K.y));
                float lo, hi; upk(lo, hi, sc);
                u64 pp = pk(ex2a(lo), ex2a(hi));
                lsA1 = add2_(lsA1, pp);
                xA1 = fma2_(pp, V.y, xA1);
                yA1 = fma2_(pp, U.y, yA1);
            }
            {
                u64 sc = fma2_(qb1.x, L.x, mul2_(qb0.x, K.x));
                float lo, hi; upk(lo, hi, sc);
                u64 pp = pk(ex2a(lo), ex2a(hi));
                lsB0 = add2_(lsB0, pp);
                xB0 = fma2_(pp, V.x, xB0);
                yB0 = fma2_(pp, U.x, yB0);
            }
            {
                u64 sc = fma2_(qb1.y, L.y, mul2_(qb0.y, K.y));
                float lo, hi; upk(lo, hi, sc);
                u64 pp = pk(ex2a(lo), ex2a(hi));
                lsB1 = add2_(lsB1, pp);
                xB1 = fma2_(pp, V.y, xB1);
                yB1 = fma2_(pp, U.y, yB1);
            }
        }
        __syncthreads();   // all q reads done before ctx overwrites q slots

        // ---- ctx writeback into q slots: floats [8*grp .. 8*grp+7] of own rows ----
        if (t0 < SS) {
            float* ro = big + t0 * ROWF + 8 * grp;
            float s0, s1; upk(s0, s1, lsA0);
            float ra = rcpa(s0), rb = rcpa(s1);
            float u0, u1, v0, v1;
            upk(u0, u1, xA0); upk(v0, v1, yA0);
            *(float4*)(ro) = make_float4(u0 * ra, v0 * ra, u1 * rb, v1 * rb);
            upk(s0, s1, lsA1);
            ra = rcpa(s0); rb = rcpa(s1);
            upk(u0, u1, xA1); upk(v0, v1, yA1);
            *(float4*)(ro + 4) = make_float4(u0 * ra, v0 * ra, u1 * rb, v1 * rb);
        }
        if (t1 < SS) {
            float* ro = big + t1 * ROWF + 8 * grp;
            float s0, s1; upk(s0, s1, lsB0);
            float ra = rcpa(s0), rb = rcpa(s1);
            float u0, u1, v0, v1;
            upk(u0, u1, xB0); upk(v0, v1, yB0);
            *(float4*)(ro) = make_float4(u0 * ra, v0 * ra, u1 * rb, v1 * rb);
            upk(s0, s1, lsB1);
            ra = rcpa(s0); rb = rcpa(s1);
            upk(u0, u1, xB1); upk(v0, v1, yB1);
            *(float4*)(ro + 4) = make_float4(u0 * ra, v0 * ra, u1 * rb, v1 * rb);
        }
        __syncthreads();

        // ---- per-token epilogue: Wo + residual + LN1, FFN + residual + LN2 ----
        if (tid < SS) {
            const float* ro = big + tid * ROWF;
            float4 c0 = *(const float4*)(ro);
            float4 c1 = *(const float4*)(ro + 4);
            float4 c2 = *(const float4*)(ro + 8);
            float4 c3 = *(const float4*)(ro + 12);
            float cx[16] = {c0.x, c0.y, c0.z, c0.w, c1.x, c1.y, c1.z, c1.w,
                            c2.x, c2.y, c2.z, c2.w, c3.x, c3.y, c3.z, c3.w};

            u64 hn2[8];
            gemm16p(cx, woT, (const u64*)b_o, hn2);
            #pragma unroll
            for (int j = 0; j < 8; j++) hn2[j] = add2_(h2[j], hn2[j]);
            ln2p(hn2, (const u64*)g1s, (const u64*)be1s);

            float hsv[16];
            #pragma unroll
            for (int j = 0; j < 8; j++) upk(hsv[2 * j], hsv[2 * j + 1], hn2[j]);
            u64 f2[8];
            gemm16p(hsv, w1T, (const u64*)b_1, f2);
            float fs[16];
            #pragma unroll
            for (int j = 0; j < 8; j++) {
                float a, b; upk(a, b, f2[j]);
                fs[2 * j]     = fmaxf(a, 0.f);
                fs[2 * j + 1] = fmaxf(b, 0.f);
            }
            u64 o2[8];
            gemm16p(fs, w2T, (const u64*)b_2, o2);
            #pragma unroll
            for (int j = 0; j < 8; j++) h2[j] = add2_(hn2[j], o2[j]);
            ln2p(h2, (const u64*)g2s, (const u64*)be2s);
        }
    }

    // ---- final LN on cls only ----
    if (tid == 0) {
        float hv[16];
        #pragma unroll
        for (int j = 0; j < 8; j++) upk(hv[2 * j], hv[2 * j + 1], h2[j]);
        float gf[DD], bf[DD];
        #pragma unroll
        for (int d = 0; d < DD; d++) { gf[d] = lnf_g[d]; bf[d] = lnf_b[d]; }
        ln16s(hv, gf, bf);
        #pragma unroll
        for (int d = 0; d < DD; d++) clat[d] = hv[d];
    }
    __syncthreads();

    if (tid < PP) {
        float acc = end_b[tid];
        const float* ew = end_w + tid * DD;
        #pragma unroll
        for (int d = 0; d < DD; d++) acc += clat[d] * ew[d];
        clat[DD + tid] = acc;
    }
    __syncthreads();

    if (tid == 0) {
        float z = head_b[0];
        #pragma unroll 4
        for (int j = 0; j < PP; j++) z += clat[DD + j] * head_w[j];
        out[bidx] = 1.0f / (1.0f + __expf(-z));
    }
}

extern "C" void kernel_launch(void* const* d_in, const int* in_sizes, int n_in,
                              void* d_out, int out_size) {
    const float* x       = (const float*)d_in[0];
    const float* conv_w  = (const float*)d_in[1];
    const float* conv_b  = (const float*)d_in[2];
    const float* cls_emb = (const float*)d_in[3];
    const float* Wqkv    = (const float*)d_in[4];
    const float* bqkv    = (const float*)d_in[5];
    const float* Wo      = (const float*)d_in[6];
    const float* bo      = (const float*)d_in[7];
    const float* W1      = (const float*)d_in[8];
    const float* b1      = (const float*)d_in[9];
    const float* W2      = (const float*)d_in[10];
    const float* b2      = (const float*)d_in[11];
    const float* ln1_g   = (const float*)d_in[12];
    const float* ln1_b   = (const float*)d_in[13];
    const float* ln2_g   = (const float*)d_in[14];
    const float* ln2_b   = (const float*)d_in[15];
    const float* lnf_g   = (const float*)d_in[16];
    const float* lnf_b   = (const float*)d_in[17];
    const float* end_w   = (const float*)d_in[18];
    const float* end_b   = (const float*)d_in[19];
    const float* head_w  = (const float*)d_in[20];
    const float* head_b  = (const float*)d_in[21];
    float* out = (float*)d_out;

    const int B = in_sizes[0] / SEQ;   // 2048
    torrin_transformer_kernel<<<B, NT>>>(
        x, conv_w, conv_b, cls_emb, Wqkv, bqkv, Wo, bo, W1, b1, W2, b2,
        ln1_g, ln1_b, ln2_g, ln2_b, lnf_g, lnf_b, end_w, end_b, head_w, head_b,
        out);
}